// round 1
// baseline (speedup 1.0000x reference)
#include <cuda_runtime.h>

typedef unsigned long long ull;

#define TX 16
#define NTOT 51840000   // 405*80*80*20

__device__ float g_mask1[6400];
__device__ float g_mask2[6400];

__global__ void mask_prep(const float* __restrict__ a1, const float* __restrict__ a2)
{
    int p = blockIdx.x * blockDim.x + threadIdx.x;
    if (p < 6400) {
        float s1 = 0.f, s2 = 0.f;
        const float* p1 = a1 + p * 20;
        const float* p2 = a2 + p * 20;
        #pragma unroll
        for (int z = 0; z < 20; ++z) { s1 += p1[z]; s2 += p2[z]; }
        g_mask1[p] = fminf(fmaxf(s1, 0.f), 1.f);
        g_mask2[p] = fminf(fmaxf(s2, 0.f), 1.f);
    }
}

__device__ __forceinline__ ull pack2(float lo, float hi) {
    ull r; asm("mov.b64 %0, {%1, %2};" : "=l"(r) : "f"(lo), "f"(hi)); return r;
}
__device__ __forceinline__ void unpack2(ull v, float& lo, float& hi) {
    asm("mov.b64 {%0, %1}, %2;" : "=f"(lo), "=f"(hi) : "l"(v));
}
__device__ __forceinline__ void fma2(ull& d, ull a, ull b) {
    asm("fma.rn.f32x2 %0, %1, %2, %0;" : "+l"(d) : "l"(a), "l"(b));
}

// smem layout:
//   f1s: [c=32][xl=16 * 20 z]            = 10240 floats (40960 B)
//   f2s: [c=32][zq=6][x2l=24][4]         = 18432 floats (73728 B)  (zz = z2+2, zero padded)
// total 114688 B -> 2 blocks / SM
__global__ void __launch_bounds__(256, 2) corr_kernel(
    const float* __restrict__ f1, const float* __restrict__ f2, float* __restrict__ out)
{
    extern __shared__ float smem[];
    float* f1s = smem;
    float* f2s = smem + 10240;

    const int x0 = blockIdx.x * TX;
    const int y  = blockIdx.y;
    const int di = blockIdx.z;
    const int y2 = y + di - 4;
    const bool yok = ((unsigned)y2 < 80u);
    const int tid = threadIdx.x;

    if (yok) {
        // ---- f1 tile: contiguous 320 floats per channel ----
        const float4* g1 = (const float4*)(f1 + y * 1600 + x0 * 20);
        for (int idx = tid; idx < 2560; idx += 256) {
            int c = idx / 80, r = idx - c * 80;
            ((float4*)f1s)[c * 80 + r] = g1[c * 32000 + r];
        }
        // ---- f2 window with spatial + depth zero padding ----
        const float* g2 = f2 + y2 * 1600;
        for (int idx = tid; idx < 18432; idx += 256) {
            int c   = idx / 576;
            int r   = idx - c * 576;      // x2l*24 + zz
            int x2l = r / 24;
            int zz  = r - x2l * 24;
            int x2g = x0 - 4 + x2l;
            int z   = zz - 2;
            float v = 0.f;
            if ((unsigned)x2g < 80u && (unsigned)z < 20u)
                v = g2[c * 128000 + x2g * 20 + z];
            f2s[((c * 6 + (zz >> 2)) * 24 + x2l) * 4 + (zz & 3)] = v;
        }
    }
    __syncthreads();

    const int tx   = tid & 15;
    const int zq   = (tid >> 4) % 5;     // z-quad: z = 4*zq .. 4*zq+3
    const int djg  = tid / 80;           // 0..2 (dj group of 3)
    const bool act = tid < 240;

    // acc[jl*10 + dk*2 + p]  p=0 -> z pair (4zq,4zq+1), p=1 -> (4zq+2,4zq+3)
    ull acc[30];
    #pragma unroll
    for (int i = 0; i < 30; ++i) acc[i] = 0ull;

    if (act && yok) {
        #pragma unroll 2
        for (int c = 0; c < 32; ++c) {
            float4 av = *(const float4*)(f1s + c * 320 + tx * 20 + 4 * zq);
            ull a01 = pack2(av.x, av.y);
            ull a23 = pack2(av.z, av.w);
            #pragma unroll
            for (int jl = 0; jl < 3; ++jl) {
                int x2l = tx + djg * 3 + jl;
                float4 b0 = *(const float4*)(f2s + ((c * 6 + zq    ) * 24 + x2l) * 4);
                float4 b4 = *(const float4*)(f2s + ((c * 6 + zq + 1) * 24 + x2l) * 4);
                ull P0 = pack2(b0.x, b0.y);
                ull P1 = pack2(b0.y, b0.z);
                ull P2 = pack2(b0.z, b0.w);
                ull P3 = pack2(b0.w, b4.x);
                ull P4 = pack2(b4.x, b4.y);
                ull P5 = pack2(b4.y, b4.z);
                ull P6 = pack2(b4.z, b4.w);
                ull* A = acc + jl * 10;
                fma2(A[0], a01, P0); fma2(A[1], a23, P2);   // dk=0
                fma2(A[2], a01, P1); fma2(A[3], a23, P3);   // dk=1
                fma2(A[4], a01, P2); fma2(A[5], a23, P4);   // dk=2
                fma2(A[6], a01, P3); fma2(A[7], a23, P5);   // dk=3
                fma2(A[8], a01, P4); fma2(A[9], a23, P6);   // dk=4
            }
        }
    }

    if (act) {
        const int x = x0 + tx;
        const float m1 = g_mask1[y * 80 + x];
        const float inv = 1.f / 32.f;
        #pragma unroll
        for (int jl = 0; jl < 3; ++jl) {
            const int dj   = djg * 3 + jl;
            const int x2g  = x + dj - 4;
            const bool spin = yok && ((unsigned)x2g < 80u);
            const float m2v = spin ? g_mask2[y2 * 80 + x2g] : 1.f;
            const float mIn = m1 * m2v;
            #pragma unroll
            for (int dk = 0; dk < 5; ++dk) {
                const int t = dk * 81 + di * 9 + dj;
                const int base = t * 128000 + y * 1600 + x * 20 + 4 * zq;
                float4 cv;
                unpack2(acc[jl * 10 + dk * 2 + 0], cv.x, cv.y);
                unpack2(acc[jl * 10 + dk * 2 + 1], cv.z, cv.w);
                cv.x *= inv; cv.y *= inv; cv.z *= inv; cv.w *= inv;
                *(float4*)(out + base) = cv;
                float4 mv;
                {
                    float* mp = (float*)&mv;
                    #pragma unroll
                    for (int zl = 0; zl < 4; ++zl) {
                        int z2 = 4 * zq + zl + dk - 2;
                        mp[zl] = (spin && (unsigned)z2 < 20u) ? mIn : m1;
                    }
                }
                *(float4*)(out + NTOT + base) = mv;
            }
        }
    }
}

extern "C" void kernel_launch(void* const* d_in, const int* in_sizes, int n_in,
                              void* d_out, int out_size)
{
    (void)in_sizes; (void)n_in; (void)out_size;
    const float* f1 = (const float*)d_in[0];
    const float* a1 = (const float*)d_in[1];
    const float* f2 = (const float*)d_in[2];
    const float* a2 = (const float*)d_in[3];
    float* out = (float*)d_out;

    cudaFuncSetAttribute(corr_kernel, cudaFuncAttributeMaxDynamicSharedMemorySize, 114688);

    mask_prep<<<25, 256>>>(a1, a2);
    corr_kernel<<<dim3(5, 80, 9), 256, 114688>>>(f1, f2, out);
}